// round 7
// baseline (speedup 1.0000x reference)
#include <cuda_runtime.h>
#include <cuda_bf16.h>
#include <math.h>
#include <cstdint>

// Model dims
#define NL 32
#define D  256
#define DI 512
#define NS 16
#define RR 16
#define KC 4
#define VV 4096
#define FF 1024
#define BB 32
#define LL 256
#define TT (BB*LL)

// ---------------- scratch ----------------------------------------------------
__device__ float g_x  [TT * D];
__device__ float g_h  [TT * D];
__device__ float g_xz [TT * 2 * DI];
__device__ float g_xc [TT * DI];
__device__ float g_dbc[TT * 48];
__device__ float g_dt [TT * DI];
__device__ float g_y  [TT * DI];
__device__ float g_h1 [TT * FF];

// ---------------- packed f32x2 helpers ---------------------------------------
#define FMA2(acc, a, b) \
    asm("fma.rn.f32x2 %0, %1, %2, %0;" : "+l"(acc) : "l"(a), "l"(b))
#define UNPACK2(lo, hi, v) \
    asm("mov.b64 {%0, %1}, %2;" : "=r"(lo), "=r"(hi) : "l"(v))

// ---------------- FFMA2 NT GEMM ----------------------------------------------
// C[m][n] = dot(A[m,:], B[n,:]) + epilogue
// BM=128, BN=128, BK=16, 256 threads, 8x8 microtile (round-4 shape).
// A is stored DUPLICATED ({a,a} float2) in smem so the mainloop has NO movs:
// per k: 4 LDS.128 (A-dup, broadcast) + 2 LDS.128 (B) + 32 FFMA2.
// EPI: 0 plain, 1 bias+relu, 2 bias, 3 residual add, 4 bias+softplus
#define BM 128
#define BN 128
#define BK 16
#define ADW (2 * BM)       // 256 floats: duplicated-A row (unpadded; reads are broadcast)
#define BSW (BN)           // 128 floats: B row (unpadded; reads conflict-free)

template<int EPI>
__global__ __launch_bounds__(256)
void gemm2(const float* __restrict__ A, int lda,
           const float* __restrict__ B, int ldb,
           float* __restrict__ C, int ldc,
           const float* __restrict__ bias,
           const float* __restrict__ res,
           int N, int K)
{
    __shared__ float Ad[2][BK][ADW];   // 32768 B
    __shared__ float Bs[2][BK][BSW];   // 16384 B   (total exactly 48 KB)

    int tid = threadIdx.x;
    int bm = blockIdx.y * BM, bn = blockIdx.x * BN;
    int tx = tid & 15, ty = tid >> 4;     // 16 x 16 threads
    int m0 = ty * 8, n0 = tx * 8;

    int lr = tid >> 2;            // 0..63
    int lk = (tid & 3) * 4;       // k sub-chunk (0,4,8,12)

    unsigned long long acc[8][4];
    #pragma unroll
    for (int i = 0; i < 8; i++)
        #pragma unroll
        for (int j = 0; j < 4; j++) acc[i][j] = 0ull;

    float4 pa[2], pb[2];

    auto fetch = [&](int k0) {
        #pragma unroll
        for (int h = 0; h < 2; h++) {
            int r = lr + h * 64;
            pa[h] = *reinterpret_cast<const float4*>(
                A + (size_t)(bm + r) * lda + k0 + lk);
            pb[h] = make_float4(0.f, 0.f, 0.f, 0.f);
            if (bn + r < N)
                pb[h] = *reinterpret_cast<const float4*>(
                    B + (size_t)(bn + r) * ldb + k0 + lk);
        }
    };
    auto stage = [&](int buf) {
        #pragma unroll
        for (int h = 0; h < 2; h++) {
            int r2 = 2 * (lr + h * 64);
            float va[4] = {pa[h].x, pa[h].y, pa[h].z, pa[h].w};
            #pragma unroll
            for (int j = 0; j < 4; j++)
                *reinterpret_cast<float2*>(&Ad[buf][lk + j][r2]) =
                    make_float2(va[j], va[j]);
        }
        #pragma unroll
        for (int h = 0; h < 2; h++) {
            int r = lr + h * 64;
            Bs[buf][lk + 0][r] = pb[h].x;
            Bs[buf][lk + 1][r] = pb[h].y;
            Bs[buf][lk + 2][r] = pb[h].z;
            Bs[buf][lk + 3][r] = pb[h].w;
        }
    };

    int NC = K / BK;
    fetch(0);
    stage(0);
    __syncthreads();

    for (int kc = 0; kc < NC; kc++) {
        int buf = kc & 1;
        if (kc + 1 < NC) fetch((kc + 1) * BK);

        #pragma unroll
        for (int k = 0; k < BK; k++) {
            // duplicated A pairs: 4 x LDS.128 -> 8 dup values (warp-broadcast)
            unsigned long long ad[8];
            #pragma unroll
            for (int i = 0; i < 8; i += 2) {
                ulonglong2 q = *reinterpret_cast<const ulonglong2*>(
                    &Ad[buf][k][2 * (m0 + i)]);
                ad[i] = q.x; ad[i + 1] = q.y;
            }
            // natural B pairs: 2 x LDS.128 -> 4 u64 (8 columns)
            ulonglong2 b0 = *reinterpret_cast<const ulonglong2*>(&Bs[buf][k][n0]);
            ulonglong2 b1 = *reinterpret_cast<const ulonglong2*>(&Bs[buf][k][n0 + 4]);
            unsigned long long bb[4] = {b0.x, b0.y, b1.x, b1.y};
            #pragma unroll
            for (int i = 0; i < 8; i++)
                #pragma unroll
                for (int j = 0; j < 4; j++)
                    FMA2(acc[i][j], ad[i], bb[j]);
        }

        if (kc + 1 < NC) {
            stage(buf ^ 1);
            __syncthreads();
        }
    }

    // ---- epilogue (pairs along N -> two contiguous float4 stores per row)
    if (bn + n0 >= N) return;   // N multiple of 8: whole group in/out
    #pragma unroll
    for (int i = 0; i < 8; i++) {
        int row = bm + m0 + i;
        float v[8];
        #pragma unroll
        for (int j = 0; j < 4; j++) {
            unsigned lo, hi;
            UNPACK2(lo, hi, acc[i][j]);
            v[2 * j]     = __uint_as_float(lo);
            v[2 * j + 1] = __uint_as_float(hi);
        }
        if (EPI == 1 || EPI == 2 || EPI == 4) {
            #pragma unroll
            for (int j = 0; j < 8; j++) v[j] += bias[bn + n0 + j];
            if (EPI == 1) {
                #pragma unroll
                for (int j = 0; j < 8; j++) v[j] = fmaxf(v[j], 0.f);
            } else if (EPI == 4) {
                #pragma unroll
                for (int j = 0; j < 8; j++)
                    v[j] = (v[j] > 20.f) ? v[j] : log1pf(expf(v[j]));
            }
        }
        size_t o = (size_t)row * ldc + bn + n0;
        if (EPI == 3) {
            float4 r0 = *reinterpret_cast<const float4*>(res + o);
            float4 r1 = *reinterpret_cast<const float4*>(res + o + 4);
            v[0] += r0.x; v[1] += r0.y; v[2] += r0.z; v[3] += r0.w;
            v[4] += r1.x; v[5] += r1.y; v[6] += r1.z; v[7] += r1.w;
        }
        *reinterpret_cast<float4*>(C + o)     = make_float4(v[0], v[1], v[2], v[3]);
        *reinterpret_cast<float4*>(C + o + 4) = make_float4(v[4], v[5], v[6], v[7]);
    }
}

// ---------------- embedding --------------------------------------------------
__global__ void embed_kernel(const int* __restrict__ tok,
                             const float* __restrict__ emb,
                             float* __restrict__ x)
{
    int t = blockIdx.x, d = threadIdx.x;
    x[t * D + d] = emb[(size_t)tok[t] * D + d];
}

// ---------------- layernorm --------------------------------------------------
__global__ void ln_kernel(const float* __restrict__ x,
                          const float* __restrict__ w,
                          const float* __restrict__ b,
                          float* __restrict__ h)
{
    int t = blockIdx.x, d = threadIdx.x;
    float v = x[t * D + d];
    float s = v, s2 = v * v;
    #pragma unroll
    for (int o = 16; o > 0; o >>= 1) {
        s  += __shfl_xor_sync(0xffffffffu, s,  o);
        s2 += __shfl_xor_sync(0xffffffffu, s2, o);
    }
    __shared__ float ws[8], ws2[8];
    int wi = d >> 5;
    if ((d & 31) == 0) { ws[wi] = s; ws2[wi] = s2; }
    __syncthreads();
    if (d < 32) {
        float a  = (d < 8) ? ws[d]  : 0.f;
        float a2 = (d < 8) ? ws2[d] : 0.f;
        #pragma unroll
        for (int o = 4; o > 0; o >>= 1) {
            a  += __shfl_xor_sync(0xffffffffu, a,  o);
            a2 += __shfl_xor_sync(0xffffffffu, a2, o);
        }
        if (d == 0) { ws[0] = a; ws2[0] = a2; }
    }
    __syncthreads();
    float mu  = ws[0] * (1.f / D);
    float var = ws2[0] * (1.f / D) - mu * mu;
    float inv = rsqrtf(var + 1e-5f);
    h[t * D + d] = (v - mu) * inv * w[d] + b[d];
}

// ---------------- causal depthwise conv1d + SiLU ----------------------------
__global__ void conv_kernel(const float* __restrict__ xz,
                            const float* __restrict__ cw,
                            const float* __restrict__ cb,
                            float* __restrict__ xc)
{
    int t = blockIdx.x;
    int e = blockIdx.y * 256 + threadIdx.x;
    int l = t & (LL - 1);
    float acc = cb[e];
    #pragma unroll
    for (int k = 0; k < KC; k++) {
        int ll = l - (KC - 1) + k;
        if (ll >= 0)
            acc = fmaf(xz[(size_t)(t - (KC - 1) + k) * (2 * DI) + e], cw[e * KC + k], acc);
    }
    float s = 1.f / (1.f + __expf(-acc));
    xc[(size_t)t * DI + e] = acc * s;
}

// ---------------- selective scan + skip + gate ------------------------------
__global__ void scan_kernel(const float* __restrict__ dbc,
                            const float* __restrict__ dtf,
                            const float* __restrict__ xc,
                            const float* __restrict__ xz,
                            const float* __restrict__ A_log,
                            const float* __restrict__ Dskip,
                            float* __restrict__ y)
{
    int b = blockIdx.y;
    int tid = threadIdx.x;
    int e = blockIdx.x * 128 + tid;
    __shared__ float sB[8][NS], sC[8][NS];

    float A[NS], h[NS];
    #pragma unroll
    for (int n = 0; n < NS; n++) {
        A[n] = -__expf(A_log[e * NS + n]);
        h[n] = 0.f;
    }
    float Ds = Dskip[e];

    for (int g = 0; g < LL / 8; g++) {
        __syncthreads();
        #pragma unroll
        for (int i = 0; i < 2; i++) {
            int id = tid + i * 128;
            int st = id >> 5, j = id & 31;
            int t = b * LL + g * 8 + st;
            float v = dbc[(size_t)t * 48 + RR + j];
            if (j < NS) sB[st][j] = v;
            else        sC[st][j - NS] = v;
        }
        __syncthreads();
        #pragma unroll
        for (int s = 0; s < 8; s++) {
            int t = b * LL + g * 8 + s;
            float dtv = dtf[(size_t)t * DI + e];
            float xv  = xc[(size_t)t * DI + e];
            float du  = dtv * xv;
            float acc = 0.f;
            #pragma unroll
            for (int n = 0; n < NS; n++) {
                float dA = __expf(dtv * A[n]);
                h[n] = fmaf(h[n], dA, du * sB[s][n]);
                acc = fmaf(h[n], sC[s][n], acc);
            }
            float zv = xz[(size_t)t * (2 * DI) + DI + e];
            float sig = 1.f / (1.f + __expf(-zv));
            y[(size_t)t * DI + e] = (acc + xv * Ds) * (zv * sig);
        }
    }
}

// ---------------- host side --------------------------------------------------
extern "C" void kernel_launch(void* const* d_in, const int* in_sizes, int n_in,
                              void* d_out, int out_size)
{
    const int*   tok    = (const int*)  d_in[0];
    const float* emb    = (const float*)d_in[1];
    const float* ln_w   = (const float*)d_in[2];
    const float* ln_b   = (const float*)d_in[3];
    const float* in_w   = (const float*)d_in[4];
    const float* conv_w = (const float*)d_in[5];
    const float* conv_b = (const float*)d_in[6];
    const float* xp_w   = (const float*)d_in[7];
    const float* dt_w   = (const float*)d_in[8];
    const float* dt_b   = (const float*)d_in[9];
    const float* A_log  = (const float*)d_in[10];
    const float* Dskip  = (const float*)d_in[11];
    const float* out_w  = (const float*)d_in[12];
    const float* W1     = (const float*)d_in[13];
    const float* b1     = (const float*)d_in[14];
    const float* W2     = (const float*)d_in[15];
    const float* b2     = (const float*)d_in[16];
    float* out = (float*)d_out;

    float *px, *ph, *pxz, *pxc, *pdbc, *pdt, *py, *ph1;
    cudaGetSymbolAddress((void**)&px,   g_x);
    cudaGetSymbolAddress((void**)&ph,   g_h);
    cudaGetSymbolAddress((void**)&pxz,  g_xz);
    cudaGetSymbolAddress((void**)&pxc,  g_xc);
    cudaGetSymbolAddress((void**)&pdbc, g_dbc);
    cudaGetSymbolAddress((void**)&pdt,  g_dt);
    cudaGetSymbolAddress((void**)&py,   g_y);
    cudaGetSymbolAddress((void**)&ph1,  g_h1);

    const int GY = TT / BM;   // 64 row-blocks

    embed_kernel<<<TT, D>>>(tok, emb, px);

    for (int l = 0; l < NL; l++) {
        const float* lw  = ln_w   + (size_t)l * D;
        const float* lb  = ln_b   + (size_t)l * D;
        const float* iw  = in_w   + (size_t)l * 2 * DI * D;
        const float* cw  = conv_w + (size_t)l * DI * KC;
        const float* cb  = conv_b + (size_t)l * DI;
        const float* xw  = xp_w   + (size_t)l * 48 * DI;
        const float* dw  = dt_w   + (size_t)l * DI * RR;
        const float* db  = dt_b   + (size_t)l * DI;
        const float* al  = A_log  + (size_t)l * DI * NS;
        const float* ds  = Dskip  + (size_t)l * DI;
        const float* ow  = out_w  + (size_t)l * D * DI;

        ln_kernel<<<TT, D>>>(px, lw, lb, ph);

        // xz = LN(x) @ in_w^T   (8192 x 1024 x 256)
        gemm2<0><<<dim3((2 * DI) / BN, GY), 256>>>(
            ph, D, iw, D, pxz, 2 * DI, nullptr, nullptr, 2 * DI, D);

        conv_kernel<<<dim3(TT, 2), 256>>>(pxz, cw, cb, pxc);

        // dbc = xc @ xp_w^T   (8192 x 48 x 512)
        gemm2<0><<<dim3(1, GY), 256>>>(
            pxc, DI, xw, DI, pdbc, 48, nullptr, nullptr, 48, DI);

        // dt = softplus(dbc[:, :16] @ dt_w^T + dt_b)   (8192 x 512 x 16)
        gemm2<4><<<dim3(DI / BN, GY), 256>>>(
            pdbc, 48, dw, RR, pdt, DI, db, nullptr, DI, RR);

        scan_kernel<<<dim3(4, BB), 128>>>(pdbc, pdt, pxc, pxz, al, ds, py);

        // x += y @ out_w^T   (8192 x 256 x 512)
        gemm2<3><<<dim3(D / BN, GY), 256>>>(
            py, DI, ow, DI, px, D, nullptr, px, D, DI);
    }

    // head
    gemm2<1><<<dim3(FF / BN, GY), 256>>>(
        px, D, W1, D, ph1, FF, b1, nullptr, FF, D);
    gemm2<2><<<dim3(VV / BN, GY), 256>>>(
        ph1, FF, W2, FF, out, VV, b2, nullptr, VV, FF);
}

// round 8
// speedup vs baseline: 1.2323x; 1.2323x over previous
#include <cuda_runtime.h>
#include <cuda_bf16.h>
#include <math.h>
#include <cstdint>

// Model dims
#define NL 32
#define D  256
#define DI 512
#define NS 16
#define RR 16
#define KC 4
#define VV 4096
#define FF 1024
#define BB 32
#define LL 256
#define TT (BB*LL)

// ---------------- scratch ----------------------------------------------------
__device__ float g_x  [TT * D];
__device__ float g_h  [TT * D];
__device__ float g_xz [TT * 2 * DI];
__device__ float g_xc [TT * DI];
__device__ float g_dbc[TT * 48];
__device__ float g_y  [TT * DI];
__device__ float g_h1 [TT * FF];

// ---------------- packed f32x2 helpers ---------------------------------------
#define PACK_AA(dst, x) \
    asm("mov.b64 %0, {%1, %1};" : "=l"(dst) : "r"(__float_as_uint(x)))
#define FMA2(acc, a, b) \
    asm("fma.rn.f32x2 %0, %1, %2, %0;" : "+l"(acc) : "l"(a), "l"(b))
#define UNPACK2(lo, hi, v) \
    asm("mov.b64 {%0, %1}, %2;" : "=r"(lo), "=r"(hi) : "l"(v))

// ---------------- FFMA2 NT GEMM ----------------------------------------------
// C[m][n] = dot(A[m,:], B[n,:]) + epilogue
// Round-4 shape: BM=BN=128, BK=16, 256 threads, 8 rows x 8 cols per thread.
// Column mapping is SPLIT: thread owns cols {4tx..4tx+3} and {64+4tx..+3} so
// the two B LDS.128 per k are bank-conflict-free (banks 4tx..4tx+3 per phase).
// EPI: 0 plain, 1 bias+relu, 2 bias, 3 residual add, 4 bias+softplus
#define BM 128
#define BN 128
#define BK 16
#define SROW 132   // padded smem row stride (floats)

template<int EPI>
__global__ __launch_bounds__(256)
void gemm2(const float* __restrict__ A, int lda,
           const float* __restrict__ B, int ldb,
           float* __restrict__ C, int ldc,
           const float* __restrict__ bias,
           const float* __restrict__ res,
           int N, int K)
{
    __shared__ float As[2][BK][SROW];   // k-major
    __shared__ float Bs[2][BK][SROW];   // k-major

    int tid = threadIdx.x;
    int bm = blockIdx.y * BM, bn = blockIdx.x * BN;
    int tx = tid & 15, ty = tid >> 4;
    int m0 = ty * 8, n0 = tx * 4;      // cols n0..n0+3 and 64+n0..64+n0+3

    int lr = tid >> 2;
    int lk = (tid & 3) * 4;

    unsigned long long acc[8][4];       // j=0,1 -> group0 ; j=2,3 -> group1
    #pragma unroll
    for (int i = 0; i < 8; i++)
        #pragma unroll
        for (int j = 0; j < 4; j++) acc[i][j] = 0ull;

    float4 pa[2], pb[2];

    auto fetch = [&](int k0) {
        #pragma unroll
        for (int h = 0; h < 2; h++) {
            int r = lr + h * 64;
            pa[h] = *reinterpret_cast<const float4*>(
                A + (size_t)(bm + r) * lda + k0 + lk);
            pb[h] = make_float4(0.f, 0.f, 0.f, 0.f);
            if (bn + r < N)
                pb[h] = *reinterpret_cast<const float4*>(
                    B + (size_t)(bn + r) * ldb + k0 + lk);
        }
    };
    auto stage = [&](int buf) {
        #pragma unroll
        for (int h = 0; h < 2; h++) {
            int r = lr + h * 64;
            As[buf][lk + 0][r] = pa[h].x;
            As[buf][lk + 1][r] = pa[h].y;
            As[buf][lk + 2][r] = pa[h].z;
            As[buf][lk + 3][r] = pa[h].w;
            Bs[buf][lk + 0][r] = pb[h].x;
            Bs[buf][lk + 1][r] = pb[h].y;
            Bs[buf][lk + 2][r] = pb[h].z;
            Bs[buf][lk + 3][r] = pb[h].w;
        }
    };

    int NC = K / BK;
    fetch(0);
    stage(0);
    __syncthreads();

    for (int kc = 0; kc < NC; kc++) {
        int buf = kc & 1;
        if (kc + 1 < NC) fetch((kc + 1) * BK);

        #pragma unroll
        for (int k = 0; k < BK; k++) {
            float4 a0 = *reinterpret_cast<const float4*>(&As[buf][k][m0]);
            float4 a1 = *reinterpret_cast<const float4*>(&As[buf][k][m0 + 4]);
            // conflict-free B reads: lane addr = tx*16B -> banks 4tx..4tx+3
            ulonglong2 q0 = *reinterpret_cast<const ulonglong2*>(&Bs[buf][k][n0]);
            ulonglong2 q1 = *reinterpret_cast<const ulonglong2*>(&Bs[buf][k][64 + n0]);
            float av[8] = {a0.x, a0.y, a0.z, a0.w, a1.x, a1.y, a1.z, a1.w};
            unsigned long long bb[4] = {q0.x, q0.y, q1.x, q1.y};
            #pragma unroll
            for (int i = 0; i < 8; i++) {
                unsigned long long aa;
                PACK_AA(aa, av[i]);
                #pragma unroll
                for (int j = 0; j < 4; j++)
                    FMA2(acc[i][j], aa, bb[j]);
            }
        }

        if (kc + 1 < NC) {
            stage(buf ^ 1);
            __syncthreads();
        }
    }

    // ---- epilogue: two float4 groups per row (cols bn+n0, bn+64+n0)
    #pragma unroll
    for (int g = 0; g < 2; g++) {
        int colb = bn + g * 64 + n0;
        if (colb >= N) continue;
        #pragma unroll
        for (int i = 0; i < 8; i++) {
            int row = bm + m0 + i;
            unsigned u0, u1, u2, u3;
            UNPACK2(u0, u1, acc[i][2 * g]);
            UNPACK2(u2, u3, acc[i][2 * g + 1]);
            float v[4] = {__uint_as_float(u0), __uint_as_float(u1),
                          __uint_as_float(u2), __uint_as_float(u3)};
            if (EPI == 1 || EPI == 2 || EPI == 4) {
                #pragma unroll
                for (int j = 0; j < 4; j++) v[j] += bias[colb + j];
                if (EPI == 1) {
                    #pragma unroll
                    for (int j = 0; j < 4; j++) v[j] = fmaxf(v[j], 0.f);
                } else if (EPI == 4) {
                    #pragma unroll
                    for (int j = 0; j < 4; j++)
                        v[j] = (v[j] > 20.f) ? v[j] : log1pf(expf(v[j]));
                }
            }
            size_t o = (size_t)row * ldc + colb;
            if (EPI == 3) {
                float4 r4 = *reinterpret_cast<const float4*>(res + o);
                v[0] += r4.x; v[1] += r4.y; v[2] += r4.z; v[3] += r4.w;
            }
            *reinterpret_cast<float4*>(C + o) = make_float4(v[0], v[1], v[2], v[3]);
        }
    }
}

// ---------------- embedding --------------------------------------------------
__global__ void embed_kernel(const int* __restrict__ tok,
                             const float* __restrict__ emb,
                             float* __restrict__ x)
{
    int t = blockIdx.x, d = threadIdx.x;
    x[t * D + d] = emb[(size_t)tok[t] * D + d];
}

// ---------------- layernorm --------------------------------------------------
__global__ void ln_kernel(const float* __restrict__ x,
                          const float* __restrict__ w,
                          const float* __restrict__ b,
                          float* __restrict__ h)
{
    int t = blockIdx.x, d = threadIdx.x;
    float v = x[t * D + d];
    float s = v, s2 = v * v;
    #pragma unroll
    for (int o = 16; o > 0; o >>= 1) {
        s  += __shfl_xor_sync(0xffffffffu, s,  o);
        s2 += __shfl_xor_sync(0xffffffffu, s2, o);
    }
    __shared__ float ws[8], ws2[8];
    int wi = d >> 5;
    if ((d & 31) == 0) { ws[wi] = s; ws2[wi] = s2; }
    __syncthreads();
    if (d < 32) {
        float a  = (d < 8) ? ws[d]  : 0.f;
        float a2 = (d < 8) ? ws2[d] : 0.f;
        #pragma unroll
        for (int o = 4; o > 0; o >>= 1) {
            a  += __shfl_xor_sync(0xffffffffu, a,  o);
            a2 += __shfl_xor_sync(0xffffffffu, a2, o);
        }
        if (d == 0) { ws[0] = a; ws2[0] = a2; }
    }
    __syncthreads();
    float mu  = ws[0] * (1.f / D);
    float var = ws2[0] * (1.f / D) - mu * mu;
    float inv = rsqrtf(var + 1e-5f);
    h[t * D + d] = (v - mu) * inv * w[d] + b[d];
}

// ---------------- causal depthwise conv1d + SiLU ----------------------------
__global__ void conv_kernel(const float* __restrict__ xz,
                            const float* __restrict__ cw,
                            const float* __restrict__ cb,
                            float* __restrict__ xc)
{
    int t = blockIdx.x;
    int e = blockIdx.y * 256 + threadIdx.x;
    int l = t & (LL - 1);
    float acc = cb[e];
    #pragma unroll
    for (int k = 0; k < KC; k++) {
        int ll = l - (KC - 1) + k;
        if (ll >= 0)
            acc = fmaf(xz[(size_t)(t - (KC - 1) + k) * (2 * DI) + e], cw[e * KC + k], acc);
    }
    float s = 1.f / (1.f + __expf(-acc));
    xc[(size_t)t * DI + e] = acc * s;
}

// ---------------- selective scan + fused dt-proj + skip + gate ---------------
// grid (4, B), 128 threads. Computes dt = softplus(dbc[:,0:16] @ dt_w^T + dt_b)
// inline (channel e's dt_w row lives in registers; dbc[t,0:48] in smem).
__global__ void scan_kernel(const float* __restrict__ dbc,
                            const float* __restrict__ dt_w,
                            const float* __restrict__ dt_b,
                            const float* __restrict__ xc,
                            const float* __restrict__ xz,
                            const float* __restrict__ A_log,
                            const float* __restrict__ Dskip,
                            float* __restrict__ y)
{
    int b = blockIdx.y;
    int tid = threadIdx.x;
    int e = blockIdx.x * 128 + tid;
    __shared__ float sBlk[8][64];   // per step: [0:16) dt-in, [16:32) B, [32:48) C

    float A[NS], h[NS], dtw[RR];
    #pragma unroll
    for (int n = 0; n < NS; n++) {
        A[n] = -__expf(A_log[e * NS + n]);
        h[n] = 0.f;
    }
    #pragma unroll
    for (int k = 0; k < RR; k++) dtw[k] = dt_w[e * RR + k];
    float dtb = dt_b[e];
    float Ds  = Dskip[e];

    for (int g = 0; g < LL / 8; g++) {
        __syncthreads();
        #pragma unroll
        for (int i = 0; i < 4; i++) {
            int id = tid + i * 128;          // 0..511
            int st = id >> 6, j = id & 63;
            if (j < 48) {
                int t = b * LL + g * 8 + st;
                sBlk[st][j] = dbc[(size_t)t * 48 + j];
            }
        }
        __syncthreads();
        #pragma unroll
        for (int s = 0; s < 8; s++) {
            int t = b * LL + g * 8 + s;
            // fused dt projection + softplus
            float dtr = dtb;
            #pragma unroll
            for (int k = 0; k < RR; k++)
                dtr = fmaf(sBlk[s][k], dtw[k], dtr);
            float dtv = (dtr > 20.f) ? dtr : log1pf(expf(dtr));

            float xv = xc[(size_t)t * DI + e];
            float du = dtv * xv;
            float acc = 0.f;
            #pragma unroll
            for (int n = 0; n < NS; n++) {
                float dA = __expf(dtv * A[n]);
                h[n] = fmaf(h[n], dA, du * sBlk[s][16 + n]);
                acc = fmaf(h[n], sBlk[s][32 + n], acc);
            }
            float zv = xz[(size_t)t * (2 * DI) + DI + e];
            float sig = 1.f / (1.f + __expf(-zv));
            y[(size_t)t * DI + e] = (acc + xv * Ds) * (zv * sig);
        }
    }
}

// ---------------- host side --------------------------------------------------
extern "C" void kernel_launch(void* const* d_in, const int* in_sizes, int n_in,
                              void* d_out, int out_size)
{
    const int*   tok    = (const int*)  d_in[0];
    const float* emb    = (const float*)d_in[1];
    const float* ln_w   = (const float*)d_in[2];
    const float* ln_b   = (const float*)d_in[3];
    const float* in_w   = (const float*)d_in[4];
    const float* conv_w = (const float*)d_in[5];
    const float* conv_b = (const float*)d_in[6];
    const float* xp_w   = (const float*)d_in[7];
    const float* dt_w   = (const float*)d_in[8];
    const float* dt_b   = (const float*)d_in[9];
    const float* A_log  = (const float*)d_in[10];
    const float* Dskip  = (const float*)d_in[11];
    const float* out_w  = (const float*)d_in[12];
    const float* W1     = (const float*)d_in[13];
    const float* b1     = (const float*)d_in[14];
    const float* W2     = (const float*)d_in[15];
    const float* b2     = (const float*)d_in[16];
    float* out = (float*)d_out;

    float *px, *ph, *pxz, *pxc, *pdbc, *py, *ph1;
    cudaGetSymbolAddress((void**)&px,   g_x);
    cudaGetSymbolAddress((void**)&ph,   g_h);
    cudaGetSymbolAddress((void**)&pxz,  g_xz);
    cudaGetSymbolAddress((void**)&pxc,  g_xc);
    cudaGetSymbolAddress((void**)&pdbc, g_dbc);
    cudaGetSymbolAddress((void**)&py,   g_y);
    cudaGetSymbolAddress((void**)&ph1,  g_h1);

    const int GY = TT / BM;   // 64 row-blocks

    embed_kernel<<<TT, D>>>(tok, emb, px);

    for (int l = 0; l < NL; l++) {
        const float* lw  = ln_w   + (size_t)l * D;
        const float* lb  = ln_b   + (size_t)l * D;
        const float* iw  = in_w   + (size_t)l * 2 * DI * D;
        const float* cw  = conv_w + (size_t)l * DI * KC;
        const float* cb  = conv_b + (size_t)l * DI;
        const float* xw  = xp_w   + (size_t)l * 48 * DI;
        const float* dw  = dt_w   + (size_t)l * DI * RR;
        const float* db  = dt_b   + (size_t)l * DI;
        const float* al  = A_log  + (size_t)l * DI * NS;
        const float* ds  = Dskip  + (size_t)l * DI;
        const float* ow  = out_w  + (size_t)l * D * DI;

        ln_kernel<<<TT, D>>>(px, lw, lb, ph);

        // xz = LN(x) @ in_w^T   (8192 x 1024 x 256)
        gemm2<0><<<dim3((2 * DI) / BN, GY), 256>>>(
            ph, D, iw, D, pxz, 2 * DI, nullptr, nullptr, 2 * DI, D);

        conv_kernel<<<dim3(TT, 2), 256>>>(pxz, cw, cb, pxc);

        // dbc = xc @ xp_w^T   (8192 x 48 x 512)
        gemm2<0><<<dim3(1, GY), 256>>>(
            pxc, DI, xw, DI, pdbc, 48, nullptr, nullptr, 48, DI);

        // scan with fused dt-projection + softplus + D-skip + SiLU(z) gate
        scan_kernel<<<dim3(4, BB), 128>>>(pdbc, dw, db, pxc, pxz, al, ds, py);

        // x += y @ out_w^T   (8192 x 256 x 512)
        gemm2<3><<<dim3(D / BN, GY), 256>>>(
            py, DI, ow, DI, px, D, nullptr, px, D, DI);
    }

    // head
    gemm2<1><<<dim3(FF / BN, GY), 256>>>(
        px, D, W1, D, ph1, FF, b1, nullptr, FF, D);
    gemm2<2><<<dim3(VV / BN, GY), 256>>>(
        ph1, FF, W2, FF, out, VV, b2, nullptr, VV, FF);
}

// round 9
// speedup vs baseline: 1.4099x; 1.1441x over previous
#include <cuda_runtime.h>
#include <cuda_bf16.h>
#include <math.h>
#include <cstdint>

// Model dims
#define NL 32
#define D  256
#define DI 512
#define NS 16
#define RR 16
#define KC 4
#define VV 4096
#define FF 1024
#define BB 32
#define LL 256
#define TT (BB*LL)

// ---------------- scratch ----------------------------------------------------
__device__ float g_x  [TT * D];
__device__ float g_h  [TT * D];
__device__ float g_xz [TT * 2 * DI];
__device__ float g_xc [TT * DI];
__device__ float g_dbc[TT * 48];
__device__ float g_y  [TT * DI];
__device__ float g_h1 [TT * FF];

// ---------------- packed f32x2 helpers ---------------------------------------
#define PACK_AA(dst, x) \
    asm("mov.b64 %0, {%1, %1};" : "=l"(dst) : "r"(__float_as_uint(x)))
#define FMA2(acc, a, b) \
    asm("fma.rn.f32x2 %0, %1, %2, %0;" : "+l"(acc) : "l"(a), "l"(b))
#define UNPACK2(lo, hi, v) \
    asm("mov.b64 {%0, %1}, %2;" : "=r"(lo), "=r"(hi) : "l"(v))

// ============================================================================
// gemm_big: BM=256, BN=128, BK=16, 256 threads, 16x8 microtile (64 FFMA2/k).
// A duplicated ({a,a}) in smem -> no movs in mainloop. Split column map
// (cols 4tx..+3 and 64+4tx..+3) -> B LDS.128 conflict-free.
// Requires N multiple of 128, M multiple of 256, K multiple of 16.
// EPI: 0 plain, 1 bias+relu, 2 bias
// ============================================================================
#define BMG 256
#define BNG 128
#define BKG 16
#define ADWG (2 * BMG + 4)   // 516 floats
#define BSWG (BNG + 4)       // 132 floats
#define SMEMG ((2 * BKG * ADWG + 2 * BKG * BSWG) * 4)   // 82944 B

template<int EPI>
__global__ __launch_bounds__(256)
void gemm_big(const float* __restrict__ A, int lda,
              const float* __restrict__ B, int ldb,
              float* __restrict__ C, int ldc,
              const float* __restrict__ bias,
              int N, int K)
{
    extern __shared__ float sm[];
    float (*Ad)[BKG][ADWG] = reinterpret_cast<float (*)[BKG][ADWG]>(sm);
    float (*Bs)[BKG][BSWG] = reinterpret_cast<float (*)[BKG][BSWG]>(sm + 2 * BKG * ADWG);

    int tid = threadIdx.x;
    int bm = blockIdx.y * BMG, bn = blockIdx.x * BNG;
    int tx = tid & 15, ty = tid >> 4;
    int m0 = ty * 16, n0 = tx * 4;

    int lr = tid >> 2;            // 0..63
    int lk = (tid & 3) * 4;

    unsigned long long acc[16][4];
    #pragma unroll
    for (int i = 0; i < 16; i++)
        #pragma unroll
        for (int j = 0; j < 4; j++) acc[i][j] = 0ull;

    float4 pa[4], pb[2];

    auto fetch = [&](int k0) {
        #pragma unroll
        for (int h = 0; h < 4; h++)
            pa[h] = *reinterpret_cast<const float4*>(
                A + (size_t)(bm + lr + h * 64) * lda + k0 + lk);
        #pragma unroll
        for (int h = 0; h < 2; h++)
            pb[h] = *reinterpret_cast<const float4*>(
                B + (size_t)(bn + lr + h * 64) * ldb + k0 + lk);
    };
    auto stage = [&](int buf) {
        #pragma unroll
        for (int h = 0; h < 4; h++) {
            int r2 = 2 * (lr + h * 64);
            float va[4] = {pa[h].x, pa[h].y, pa[h].z, pa[h].w};
            #pragma unroll
            for (int j = 0; j < 4; j++)
                *reinterpret_cast<float2*>(&Ad[buf][lk + j][r2]) =
                    make_float2(va[j], va[j]);
        }
        #pragma unroll
        for (int h = 0; h < 2; h++) {
            int r = lr + h * 64;
            Bs[buf][lk + 0][r] = pb[h].x;
            Bs[buf][lk + 1][r] = pb[h].y;
            Bs[buf][lk + 2][r] = pb[h].z;
            Bs[buf][lk + 3][r] = pb[h].w;
        }
    };

    int NC = K / BKG;
    fetch(0);
    stage(0);
    __syncthreads();

    for (int kc = 0; kc < NC; kc++) {
        int buf = kc & 1;
        if (kc + 1 < NC) fetch((kc + 1) * BKG);

        #pragma unroll
        for (int k = 0; k < BKG; k++) {
            unsigned long long ad[16];
            #pragma unroll
            for (int i = 0; i < 8; i++) {
                ulonglong2 q = *reinterpret_cast<const ulonglong2*>(
                    &Ad[buf][k][2 * (m0 + 2 * i)]);
                ad[2 * i] = q.x; ad[2 * i + 1] = q.y;
            }
            ulonglong2 q0 = *reinterpret_cast<const ulonglong2*>(&Bs[buf][k][n0]);
            ulonglong2 q1 = *reinterpret_cast<const ulonglong2*>(&Bs[buf][k][64 + n0]);
            unsigned long long bb[4] = {q0.x, q0.y, q1.x, q1.y};
            #pragma unroll
            for (int i = 0; i < 16; i++)
                #pragma unroll
                for (int j = 0; j < 4; j++)
                    FMA2(acc[i][j], ad[i], bb[j]);
        }

        if (kc + 1 < NC) {
            stage(buf ^ 1);
            __syncthreads();
        }
    }

    // ---- epilogue: two column groups per row
    #pragma unroll
    for (int g = 0; g < 2; g++) {
        int colb = bn + g * 64 + n0;
        if (colb >= N) continue;
        #pragma unroll
        for (int i = 0; i < 16; i++) {
            int row = bm + m0 + i;
            unsigned u0, u1, u2, u3;
            UNPACK2(u0, u1, acc[i][2 * g]);
            UNPACK2(u2, u3, acc[i][2 * g + 1]);
            float v[4] = {__uint_as_float(u0), __uint_as_float(u1),
                          __uint_as_float(u2), __uint_as_float(u3)};
            if (EPI == 1 || EPI == 2) {
                #pragma unroll
                for (int j = 0; j < 4; j++) v[j] += bias[colb + j];
                if (EPI == 1) {
                    #pragma unroll
                    for (int j = 0; j < 4; j++) v[j] = fmaxf(v[j], 0.f);
                }
            }
            *reinterpret_cast<float4*>(C + (size_t)row * ldc + colb) =
                make_float4(v[0], v[1], v[2], v[3]);
        }
    }
}

// ============================================================================
// gemm2 (round-8, proven): BM=BN=128, BK=16, 256 threads, 8x8, split colmap.
// EPI: 0 plain, 3 residual add
// ============================================================================
#define BM 128
#define BN 128
#define BK 16
#define SROW 132

template<int EPI>
__global__ __launch_bounds__(256)
void gemm2(const float* __restrict__ A, int lda,
           const float* __restrict__ B, int ldb,
           float* __restrict__ C, int ldc,
           const float* __restrict__ res,
           int N, int K)
{
    __shared__ float As[2][BK][SROW];
    __shared__ float Bs[2][BK][SROW];

    int tid = threadIdx.x;
    int bm = blockIdx.y * BM, bn = blockIdx.x * BN;
    int tx = tid & 15, ty = tid >> 4;
    int m0 = ty * 8, n0 = tx * 4;

    int lr = tid >> 2;
    int lk = (tid & 3) * 4;

    unsigned long long acc[8][4];
    #pragma unroll
    for (int i = 0; i < 8; i++)
        #pragma unroll
        for (int j = 0; j < 4; j++) acc[i][j] = 0ull;

    float4 pa[2], pb[2];

    auto fetch = [&](int k0) {
        #pragma unroll
        for (int h = 0; h < 2; h++) {
            int r = lr + h * 64;
            pa[h] = *reinterpret_cast<const float4*>(
                A + (size_t)(bm + r) * lda + k0 + lk);
            pb[h] = make_float4(0.f, 0.f, 0.f, 0.f);
            if (bn + r < N)
                pb[h] = *reinterpret_cast<const float4*>(
                    B + (size_t)(bn + r) * ldb + k0 + lk);
        }
    };
    auto stage = [&](int buf) {
        #pragma unroll
        for (int h = 0; h < 2; h++) {
            int r = lr + h * 64;
            As[buf][lk + 0][r] = pa[h].x;
            As[buf][lk + 1][r] = pa[h].y;
            As[buf][lk + 2][r] = pa[h].z;
            As[buf][lk + 3][r] = pa[h].w;
            Bs[buf][lk + 0][r] = pb[h].x;
            Bs[buf][lk + 1][r] = pb[h].y;
            Bs[buf][lk + 2][r] = pb[h].z;
            Bs[buf][lk + 3][r] = pb[h].w;
        }
    };

    int NC = K / BK;
    fetch(0);
    stage(0);
    __syncthreads();

    for (int kc = 0; kc < NC; kc++) {
        int buf = kc & 1;
        if (kc + 1 < NC) fetch((kc + 1) * BK);

        #pragma unroll
        for (int k = 0; k < BK; k++) {
            float4 a0 = *reinterpret_cast<const float4*>(&As[buf][k][m0]);
            float4 a1 = *reinterpret_cast<const float4*>(&As[buf][k][m0 + 4]);
            ulonglong2 q0 = *reinterpret_cast<const ulonglong2*>(&Bs[buf][k][n0]);
            ulonglong2 q1 = *reinterpret_cast<const ulonglong2*>(&Bs[buf][k][64 + n0]);
            float av[8] = {a0.x, a0.y, a0.z, a0.w, a1.x, a1.y, a1.z, a1.w};
            unsigned long long bb[4] = {q0.x, q0.y, q1.x, q1.y};
            #pragma unroll
            for (int i = 0; i < 8; i++) {
                unsigned long long aa;
                PACK_AA(aa, av[i]);
                #pragma unroll
                for (int j = 0; j < 4; j++)
                    FMA2(acc[i][j], aa, bb[j]);
            }
        }

        if (kc + 1 < NC) {
            stage(buf ^ 1);
            __syncthreads();
        }
    }

    #pragma unroll
    for (int g = 0; g < 2; g++) {
        int colb = bn + g * 64 + n0;
        if (colb >= N) continue;
        #pragma unroll
        for (int i = 0; i < 8; i++) {
            int row = bm + m0 + i;
            unsigned u0, u1, u2, u3;
            UNPACK2(u0, u1, acc[i][2 * g]);
            UNPACK2(u2, u3, acc[i][2 * g + 1]);
            float v[4] = {__uint_as_float(u0), __uint_as_float(u1),
                          __uint_as_float(u2), __uint_as_float(u3)};
            size_t o = (size_t)row * ldc + colb;
            if (EPI == 3) {
                float4 r4 = *reinterpret_cast<const float4*>(res + o);
                v[0] += r4.x; v[1] += r4.y; v[2] += r4.z; v[3] += r4.w;
            }
            *reinterpret_cast<float4*>(C + o) = make_float4(v[0], v[1], v[2], v[3]);
        }
    }
}

// ---------------- embedding --------------------------------------------------
__global__ void embed_kernel(const int* __restrict__ tok,
                             const float* __restrict__ emb,
                             float* __restrict__ x)
{
    int t = blockIdx.x, d = threadIdx.x;
    x[t * D + d] = emb[(size_t)tok[t] * D + d];
}

// ---------------- layernorm --------------------------------------------------
__global__ void ln_kernel(const float* __restrict__ x,
                          const float* __restrict__ w,
                          const float* __restrict__ b,
                          float* __restrict__ h)
{
    int t = blockIdx.x, d = threadIdx.x;
    float v = x[t * D + d];
    float s = v, s2 = v * v;
    #pragma unroll
    for (int o = 16; o > 0; o >>= 1) {
        s  += __shfl_xor_sync(0xffffffffu, s,  o);
        s2 += __shfl_xor_sync(0xffffffffu, s2, o);
    }
    __shared__ float ws[8], ws2[8];
    int wi = d >> 5;
    if ((d & 31) == 0) { ws[wi] = s; ws2[wi] = s2; }
    __syncthreads();
    if (d < 32) {
        float a  = (d < 8) ? ws[d]  : 0.f;
        float a2 = (d < 8) ? ws2[d] : 0.f;
        #pragma unroll
        for (int o = 4; o > 0; o >>= 1) {
            a  += __shfl_xor_sync(0xffffffffu, a,  o);
            a2 += __shfl_xor_sync(0xffffffffu, a2, o);
        }
        if (d == 0) { ws[0] = a; ws2[0] = a2; }
    }
    __syncthreads();
    float mu  = ws[0] * (1.f / D);
    float var = ws2[0] * (1.f / D) - mu * mu;
    float inv = rsqrtf(var + 1e-5f);
    h[t * D + d] = (v - mu) * inv * w[d] + b[d];
}

// ---------------- causal depthwise conv1d + SiLU ----------------------------
__global__ void conv_kernel(const float* __restrict__ xz,
                            const float* __restrict__ cw,
                            const float* __restrict__ cb,
                            float* __restrict__ xc)
{
    int t = blockIdx.x;
    int e = blockIdx.y * 256 + threadIdx.x;
    int l = t & (LL - 1);
    float acc = cb[e];
    #pragma unroll
    for (int k = 0; k < KC; k++) {
        int ll = l - (KC - 1) + k;
        if (ll >= 0)
            acc = fmaf(xz[(size_t)(t - (KC - 1) + k) * (2 * DI) + e], cw[e * KC + k], acc);
    }
    float s = 1.f / (1.f + __expf(-acc));
    xc[(size_t)t * DI + e] = acc * s;
}

// ---------------- selective scan + fused dt-proj + skip + gate ---------------
__global__ void scan_kernel(const float* __restrict__ dbc,
                            const float* __restrict__ dt_w,
                            const float* __restrict__ dt_b,
                            const float* __restrict__ xc,
                            const float* __restrict__ xz,
                            const float* __restrict__ A_log,
                            const float* __restrict__ Dskip,
                            float* __restrict__ y)
{
    int b = blockIdx.y;
    int tid = threadIdx.x;
    int e = blockIdx.x * 128 + tid;
    __shared__ float sBlk[8][64];

    float A[NS], h[NS], dtw[RR];
    #pragma unroll
    for (int n = 0; n < NS; n++) {
        A[n] = -__expf(A_log[e * NS + n]);
        h[n] = 0.f;
    }
    #pragma unroll
    for (int k = 0; k < RR; k++) dtw[k] = dt_w[e * RR + k];
    float dtb = dt_b[e];
    float Ds  = Dskip[e];

    for (int g = 0; g < LL / 8; g++) {
        __syncthreads();
        #pragma unroll
        for (int i = 0; i < 4; i++) {
            int id = tid + i * 128;
            int st = id >> 6, j = id & 63;
            if (j < 48) {
                int t = b * LL + g * 8 + st;
                sBlk[st][j] = dbc[(size_t)t * 48 + j];
            }
        }
        // prefetch the group's xv/zv up front (MLP 16, hides L2 latency)
        float xv8[8], zv8[8];
        #pragma unroll
        for (int s = 0; s < 8; s++) {
            int t = b * LL + g * 8 + s;
            xv8[s] = xc[(size_t)t * DI + e];
            zv8[s] = xz[(size_t)t * (2 * DI) + DI + e];
        }
        __syncthreads();
        #pragma unroll
        for (int s = 0; s < 8; s++) {
            int t = b * LL + g * 8 + s;
            float dtr = dtb;
            #pragma unroll
            for (int k = 0; k < RR; k++)
                dtr = fmaf(sBlk[s][k], dtw[k], dtr);
            float dtv = (dtr > 20.f) ? dtr : log1pf(expf(dtr));

            float xv = xv8[s];
            float du = dtv * xv;
            float acc = 0.f;
            #pragma unroll
            for (int n = 0; n < NS; n++) {
                float dA = __expf(dtv * A[n]);
                h[n] = fmaf(h[n], dA, du * sBlk[s][16 + n]);
                acc = fmaf(h[n], sBlk[s][32 + n], acc);
            }
            float zv = zv8[s];
            float sig = 1.f / (1.f + __expf(-zv));
            y[(size_t)t * DI + e] = (acc + xv * Ds) * (zv * sig);
        }
    }
}

// ---------------- host side --------------------------------------------------
extern "C" void kernel_launch(void* const* d_in, const int* in_sizes, int n_in,
                              void* d_out, int out_size)
{
    const int*   tok    = (const int*)  d_in[0];
    const float* emb    = (const float*)d_in[1];
    const float* ln_w   = (const float*)d_in[2];
    const float* ln_b   = (const float*)d_in[3];
    const float* in_w   = (const float*)d_in[4];
    const float* conv_w = (const float*)d_in[5];
    const float* conv_b = (const float*)d_in[6];
    const float* xp_w   = (const float*)d_in[7];
    const float* dt_w   = (const float*)d_in[8];
    const float* dt_b   = (const float*)d_in[9];
    const float* A_log  = (const float*)d_in[10];
    const float* Dskip  = (const float*)d_in[11];
    const float* out_w  = (const float*)d_in[12];
    const float* W1     = (const float*)d_in[13];
    const float* b1     = (const float*)d_in[14];
    const float* W2     = (const float*)d_in[15];
    const float* b2     = (const float*)d_in[16];
    float* out = (float*)d_out;

    cudaFuncSetAttribute(gemm_big<0>, cudaFuncAttributeMaxDynamicSharedMemorySize, SMEMG);
    cudaFuncSetAttribute(gemm_big<1>, cudaFuncAttributeMaxDynamicSharedMemorySize, SMEMG);
    cudaFuncSetAttribute(gemm_big<2>, cudaFuncAttributeMaxDynamicSharedMemorySize, SMEMG);

    float *px, *ph, *pxz, *pxc, *pdbc, *py, *ph1;
    cudaGetSymbolAddress((void**)&px,   g_x);
    cudaGetSymbolAddress((void**)&ph,   g_h);
    cudaGetSymbolAddress((void**)&pxz,  g_xz);
    cudaGetSymbolAddress((void**)&pxc,  g_xc);
    cudaGetSymbolAddress((void**)&pdbc, g_dbc);
    cudaGetSymbolAddress((void**)&py,   g_y);
    cudaGetSymbolAddress((void**)&ph1,  g_h1);

    embed_kernel<<<TT, D>>>(tok, emb, px);

    for (int l = 0; l < NL; l++) {
        const float* lw  = ln_w   + (size_t)l * D;
        const float* lb  = ln_b   + (size_t)l * D;
        const float* iw  = in_w   + (size_t)l * 2 * DI * D;
        const float* cw  = conv_w + (size_t)l * DI * KC;
        const float* cb  = conv_b + (size_t)l * DI;
        const float* xw  = xp_w   + (size_t)l * 48 * DI;
        const float* dw  = dt_w   + (size_t)l * DI * RR;
        const float* db  = dt_b   + (size_t)l * DI;
        const float* al  = A_log  + (size_t)l * DI * NS;
        const float* ds  = Dskip  + (size_t)l * DI;
        const float* ow  = out_w  + (size_t)l * D * DI;

        ln_kernel<<<TT, D>>>(px, lw, lb, ph);

        // xz = LN(x) @ in_w^T   (8192 x 1024 x 256)  [big tile]
        gemm_big<0><<<dim3((2 * DI) / BNG, TT / BMG), 256, SMEMG>>>(
            ph, D, iw, D, pxz, 2 * DI, nullptr, 2 * DI, D);

        conv_kernel<<<dim3(TT, 2), 256>>>(pxz, cw, cb, pxc);

        // dbc = xc @ xp_w^T   (8192 x 48 x 512)
        gemm2<0><<<dim3(1, TT / BM), 256>>>(
            pxc, DI, xw, DI, pdbc, 48, nullptr, 48, DI);

        // scan with fused dt-projection
        scan_kernel<<<dim3(4, BB), 128>>>(pdbc, dw, db, pxc, pxz, al, ds, py);

        // x += y @ out_w^T   (8192 x 256 x 512)
        gemm2<3><<<dim3(D / BN, TT / BM), 256>>>(
            py, DI, ow, DI, px, D, px, D, DI);
    }

    // head: h1 = relu(x @ W1^T + b1)  [big tile]
    gemm_big<1><<<dim3(FF / BNG, TT / BMG), 256, SMEMG>>>(
        px, D, W1, D, ph1, FF, b1, FF, D);
    // logits = h1 @ W2^T + b2  [big tile]
    gemm_big<2><<<dim3(VV / BNG, TT / BMG), 256, SMEMG>>>(
        ph1, FF, W2, FF, out, VV, b2, VV, FF);
}

// round 10
// speedup vs baseline: 1.4638x; 1.0382x over previous
#include <cuda_runtime.h>
#include <cuda_bf16.h>
#include <math.h>
#include <cstdint>

// Model dims
#define NL 32
#define D  256
#define DI 512
#define NS 16
#define RR 16
#define KC 4
#define VV 4096
#define FF 1024
#define BB 32
#define LL 256
#define TT (BB*LL)

// ---------------- scratch ----------------------------------------------------
__device__ float g_x  [TT * D];
__device__ float g_h  [TT * D];
__device__ float g_xz [TT * 2 * DI];
__device__ float g_xc [TT * DI];
__device__ float g_dbc[TT * 48];
__device__ float g_y  [TT * DI];
__device__ float g_h1 [TT * FF];

// ---------------- packed f32x2 helpers ---------------------------------------
#define PACK_AA(dst, x) \
    asm("mov.b64 %0, {%1, %1};" : "=l"(dst) : "r"(__float_as_uint(x)))
#define FMA2(acc, a, b) \
    asm("fma.rn.f32x2 %0, %1, %2, %0;" : "+l"(acc) : "l"(a), "l"(b))
#define UNPACK2(lo, hi, v) \
    asm("mov.b64 {%0, %1}, %2;" : "=r"(lo), "=r"(hi) : "l"(v))

// ============================================================================
// gemm_big: BM=256, BN=128, BK=16, 256 threads, 16x8 microtile (64 FFMA2/k).
// (round-9 proven) EPI: 0 plain, 1 bias+relu, 2 bias
// ============================================================================
#define BMG 256
#define BNG 128
#define BKG 16
#define ADWG (2 * BMG + 4)
#define BSWG (BNG + 4)
#define SMEMG ((2 * BKG * ADWG + 2 * BKG * BSWG) * 4)   // 82944 B

template<int EPI>
__global__ __launch_bounds__(256)
void gemm_big(const float* __restrict__ A, int lda,
              const float* __restrict__ B, int ldb,
              float* __restrict__ C, int ldc,
              const float* __restrict__ bias,
              int N, int K)
{
    extern __shared__ float sm[];
    float (*Ad)[BKG][ADWG] = reinterpret_cast<float (*)[BKG][ADWG]>(sm);
    float (*Bs)[BKG][BSWG] = reinterpret_cast<float (*)[BKG][BSWG]>(sm + 2 * BKG * ADWG);

    int tid = threadIdx.x;
    int bm = blockIdx.y * BMG, bn = blockIdx.x * BNG;
    int tx = tid & 15, ty = tid >> 4;
    int m0 = ty * 16, n0 = tx * 4;

    int lr = tid >> 2;
    int lk = (tid & 3) * 4;

    unsigned long long acc[16][4];
    #pragma unroll
    for (int i = 0; i < 16; i++)
        #pragma unroll
        for (int j = 0; j < 4; j++) acc[i][j] = 0ull;

    float4 pa[4], pb[2];

    auto fetch = [&](int k0) {
        #pragma unroll
        for (int h = 0; h < 4; h++)
            pa[h] = *reinterpret_cast<const float4*>(
                A + (size_t)(bm + lr + h * 64) * lda + k0 + lk);
        #pragma unroll
        for (int h = 0; h < 2; h++)
            pb[h] = *reinterpret_cast<const float4*>(
                B + (size_t)(bn + lr + h * 64) * ldb + k0 + lk);
    };
    auto stage = [&](int buf) {
        #pragma unroll
        for (int h = 0; h < 4; h++) {
            int r2 = 2 * (lr + h * 64);
            float va[4] = {pa[h].x, pa[h].y, pa[h].z, pa[h].w};
            #pragma unroll
            for (int j = 0; j < 4; j++)
                *reinterpret_cast<float2*>(&Ad[buf][lk + j][r2]) =
                    make_float2(va[j], va[j]);
        }
        #pragma unroll
        for (int h = 0; h < 2; h++) {
            int r = lr + h * 64;
            Bs[buf][lk + 0][r] = pb[h].x;
            Bs[buf][lk + 1][r] = pb[h].y;
            Bs[buf][lk + 2][r] = pb[h].z;
            Bs[buf][lk + 3][r] = pb[h].w;
        }
    };

    int NC = K / BKG;
    fetch(0);
    stage(0);
    __syncthreads();

    for (int kc = 0; kc < NC; kc++) {
        int buf = kc & 1;
        if (kc + 1 < NC) fetch((kc + 1) * BKG);

        #pragma unroll
        for (int k = 0; k < BKG; k++) {
            unsigned long long ad[16];
            #pragma unroll
            for (int i = 0; i < 8; i++) {
                ulonglong2 q = *reinterpret_cast<const ulonglong2*>(
                    &Ad[buf][k][2 * (m0 + 2 * i)]);
                ad[2 * i] = q.x; ad[2 * i + 1] = q.y;
            }
            ulonglong2 q0 = *reinterpret_cast<const ulonglong2*>(&Bs[buf][k][n0]);
            ulonglong2 q1 = *reinterpret_cast<const ulonglong2*>(&Bs[buf][k][64 + n0]);
            unsigned long long bb[4] = {q0.x, q0.y, q1.x, q1.y};
            #pragma unroll
            for (int i = 0; i < 16; i++)
                #pragma unroll
                for (int j = 0; j < 4; j++)
                    FMA2(acc[i][j], ad[i], bb[j]);
        }

        if (kc + 1 < NC) {
            stage(buf ^ 1);
            __syncthreads();
        }
    }

    #pragma unroll
    for (int g = 0; g < 2; g++) {
        int colb = bn + g * 64 + n0;
        if (colb >= N) continue;
        #pragma unroll
        for (int i = 0; i < 16; i++) {
            int row = bm + m0 + i;
            unsigned u0, u1, u2, u3;
            UNPACK2(u0, u1, acc[i][2 * g]);
            UNPACK2(u2, u3, acc[i][2 * g + 1]);
            float v[4] = {__uint_as_float(u0), __uint_as_float(u1),
                          __uint_as_float(u2), __uint_as_float(u3)};
            if (EPI == 1 || EPI == 2) {
                #pragma unroll
                for (int j = 0; j < 4; j++) v[j] += bias[colb + j];
                if (EPI == 1) {
                    #pragma unroll
                    for (int j = 0; j < 4; j++) v[j] = fmaxf(v[j], 0.f);
                }
            }
            *reinterpret_cast<float4*>(C + (size_t)row * ldc + colb) =
                make_float4(v[0], v[1], v[2], v[3]);
        }
    }
}

// ============================================================================
// gemm_bigR: BM=128, BN=128, BK=16, 128 threads, 16x8 microtile.
// Same recipe as gemm_big but half the CTA: grid gets 2x blocks for small-N
// GEMMs (out_proj). EPI: 3 residual add.
// ============================================================================
#define BMR 128
#define ADWR (2 * BMR + 4)   // 260
#define BSWR (BNG + 4)       // 132
#define SMEMR ((2 * BKG * ADWR + 2 * BKG * BSWR) * 4)   // 50176 B

template<int EPI>
__global__ __launch_bounds__(128, 2)
void gemm_bigR(const float* __restrict__ A, int lda,
               const float* __restrict__ B, int ldb,
               float* __restrict__ C, int ldc,
               const float* __restrict__ res,
               int N, int K)
{
    extern __shared__ float sm[];
    float (*Ad)[BKG][ADWR] = reinterpret_cast<float (*)[BKG][ADWR]>(sm);
    float (*Bs)[BKG][BSWR] = reinterpret_cast<float (*)[BKG][BSWR]>(sm + 2 * BKG * ADWR);

    int tid = threadIdx.x;
    int bm = blockIdx.y * BMR, bn = blockIdx.x * BNG;
    int tx = tid & 15, ty = tid >> 4;    // 16 x 8
    int m0 = ty * 16, n0 = tx * 4;

    int lr = tid >> 2;            // 0..31
    int lk = (tid & 3) * 4;

    unsigned long long acc[16][4];
    #pragma unroll
    for (int i = 0; i < 16; i++)
        #pragma unroll
        for (int j = 0; j < 4; j++) acc[i][j] = 0ull;

    float4 pa[4], pb[4];

    auto fetch = [&](int k0) {
        #pragma unroll
        for (int h = 0; h < 4; h++)
            pa[h] = *reinterpret_cast<const float4*>(
                A + (size_t)(bm + lr + h * 32) * lda + k0 + lk);
        #pragma unroll
        for (int h = 0; h < 4; h++)
            pb[h] = *reinterpret_cast<const float4*>(
                B + (size_t)(bn + lr + h * 32) * ldb + k0 + lk);
    };
    auto stage = [&](int buf) {
        #pragma unroll
        for (int h = 0; h < 4; h++) {
            int r2 = 2 * (lr + h * 32);
            float va[4] = {pa[h].x, pa[h].y, pa[h].z, pa[h].w};
            #pragma unroll
            for (int j = 0; j < 4; j++)
                *reinterpret_cast<float2*>(&Ad[buf][lk + j][r2]) =
                    make_float2(va[j], va[j]);
        }
        #pragma unroll
        for (int h = 0; h < 4; h++) {
            int r = lr + h * 32;
            Bs[buf][lk + 0][r] = pb[h].x;
            Bs[buf][lk + 1][r] = pb[h].y;
            Bs[buf][lk + 2][r] = pb[h].z;
            Bs[buf][lk + 3][r] = pb[h].w;
        }
    };

    int NC = K / BKG;
    fetch(0);
    stage(0);
    __syncthreads();

    for (int kc = 0; kc < NC; kc++) {
        int buf = kc & 1;
        if (kc + 1 < NC) fetch((kc + 1) * BKG);

        #pragma unroll
        for (int k = 0; k < BKG; k++) {
            unsigned long long ad[16];
            #pragma unroll
            for (int i = 0; i < 8; i++) {
                ulonglong2 q = *reinterpret_cast<const ulonglong2*>(
                    &Ad[buf][k][2 * (m0 + 2 * i)]);
                ad[2 * i] = q.x; ad[2 * i + 1] = q.y;
            }
            ulonglong2 q0 = *reinterpret_cast<const ulonglong2*>(&Bs[buf][k][n0]);
            ulonglong2 q1 = *reinterpret_cast<const ulonglong2*>(&Bs[buf][k][64 + n0]);
            unsigned long long bb[4] = {q0.x, q0.y, q1.x, q1.y};
            #pragma unroll
            for (int i = 0; i < 16; i++)
                #pragma unroll
                for (int j = 0; j < 4; j++)
                    FMA2(acc[i][j], ad[i], bb[j]);
        }

        if (kc + 1 < NC) {
            stage(buf ^ 1);
            __syncthreads();
        }
    }

    #pragma unroll
    for (int g = 0; g < 2; g++) {
        int colb = bn + g * 64 + n0;
        if (colb >= N) continue;
        #pragma unroll
        for (int i = 0; i < 16; i++) {
            int row = bm + m0 + i;
            unsigned u0, u1, u2, u3;
            UNPACK2(u0, u1, acc[i][2 * g]);
            UNPACK2(u2, u3, acc[i][2 * g + 1]);
            float v[4] = {__uint_as_float(u0), __uint_as_float(u1),
                          __uint_as_float(u2), __uint_as_float(u3)};
            size_t o = (size_t)row * ldc + colb;
            if (EPI == 3) {
                float4 r4 = *reinterpret_cast<const float4*>(res + o);
                v[0] += r4.x; v[1] += r4.y; v[2] += r4.z; v[3] += r4.w;
            }
            *reinterpret_cast<float4*>(C + o) = make_float4(v[0], v[1], v[2], v[3]);
        }
    }
}

// ============================================================================
// gemm2<EPI, TBM>: BN=128, BK=16, 256 threads, TBM/16 x 8 microtile,
// split colmap (round-8 proven). EPI: 0 plain, 3 residual add.
// ============================================================================
#define BN2 128
#define BK2 16
#define SROW 132

template<int EPI, int TBM>
__global__ __launch_bounds__(256)
void gemm2(const float* __restrict__ A, int lda,
           const float* __restrict__ B, int ldb,
           float* __restrict__ C, int ldc,
           const float* __restrict__ res,
           int N, int K)
{
    constexpr int MR = TBM / 16;      // rows per thread (8 or 4)
    constexpr int AH = TBM / 64;      // A float4s per thread (2 or 1)

    __shared__ float As[2][BK2][SROW];
    __shared__ float Bs[2][BK2][SROW];

    int tid = threadIdx.x;
    int bm = blockIdx.y * TBM, bn = blockIdx.x * BN2;
    int tx = tid & 15, ty = tid >> 4;
    int m0 = ty * MR, n0 = tx * 4;

    int lr = tid >> 2;
    int lk = (tid & 3) * 4;

    unsigned long long acc[MR][4];
    #pragma unroll
    for (int i = 0; i < MR; i++)
        #pragma unroll
        for (int j = 0; j < 4; j++) acc[i][j] = 0ull;

    float4 pa[AH], pb[2];

    auto fetch = [&](int k0) {
        #pragma unroll
        for (int h = 0; h < AH; h++)
            pa[h] = *reinterpret_cast<const float4*>(
                A + (size_t)(bm + lr + h * 64) * lda + k0 + lk);
        #pragma unroll
        for (int h = 0; h < 2; h++) {
            int r = lr + h * 64;
            pb[h] = make_float4(0.f, 0.f, 0.f, 0.f);
            if (bn + r < N)
                pb[h] = *reinterpret_cast<const float4*>(
                    B + (size_t)(bn + r) * ldb + k0 + lk);
        }
    };
    auto stage = [&](int buf) {
        #pragma unroll
        for (int h = 0; h < AH; h++) {
            int r = lr + h * 64;
            As[buf][lk + 0][r] = pa[h].x;
            As[buf][lk + 1][r] = pa[h].y;
            As[buf][lk + 2][r] = pa[h].z;
            As[buf][lk + 3][r] = pa[h].w;
        }
        #pragma unroll
        for (int h = 0; h < 2; h++) {
            int r = lr + h * 64;
            Bs[buf][lk + 0][r] = pb[h].x;
            Bs[buf][lk + 1][r] = pb[h].y;
            Bs[buf][lk + 2][r] = pb[h].z;
            Bs[buf][lk + 3][r] = pb[h].w;
        }
    };

    int NC = K / BK2;
    fetch(0);
    stage(0);
    __syncthreads();

    for (int kc = 0; kc < NC; kc++) {
        int buf = kc & 1;
        if (kc + 1 < NC) fetch((kc + 1) * BK2);

        #pragma unroll
        for (int k = 0; k < BK2; k++) {
            float av[MR];
            #pragma unroll
            for (int q = 0; q < MR / 4; q++) {
                float4 a4 = *reinterpret_cast<const float4*>(&As[buf][k][m0 + q * 4]);
                av[q * 4 + 0] = a4.x; av[q * 4 + 1] = a4.y;
                av[q * 4 + 2] = a4.z; av[q * 4 + 3] = a4.w;
            }
            ulonglong2 q0 = *reinterpret_cast<const ulonglong2*>(&Bs[buf][k][n0]);
            ulonglong2 q1 = *reinterpret_cast<const ulonglong2*>(&Bs[buf][k][64 + n0]);
            unsigned long long bb[4] = {q0.x, q0.y, q1.x, q1.y};
            #pragma unroll
            for (int i = 0; i < MR; i++) {
                unsigned long long aa;
                PACK_AA(aa, av[i]);
                #pragma unroll
                for (int j = 0; j < 4; j++)
                    FMA2(acc[i][j], aa, bb[j]);
            }
        }

        if (kc + 1 < NC) {
            stage(buf ^ 1);
            __syncthreads();
        }
    }

    #pragma unroll
    for (int g = 0; g < 2; g++) {
        int colb = bn + g * 64 + n0;
        if (colb >= N) continue;
        #pragma unroll
        for (int i = 0; i < MR; i++) {
            int row = bm + m0 + i;
            unsigned u0, u1, u2, u3;
            UNPACK2(u0, u1, acc[i][2 * g]);
            UNPACK2(u2, u3, acc[i][2 * g + 1]);
            float v[4] = {__uint_as_float(u0), __uint_as_float(u1),
                          __uint_as_float(u2), __uint_as_float(u3)};
            size_t o = (size_t)row * ldc + colb;
            if (EPI == 3) {
                float4 r4 = *reinterpret_cast<const float4*>(res + o);
                v[0] += r4.x; v[1] += r4.y; v[2] += r4.z; v[3] += r4.w;
            }
            *reinterpret_cast<float4*>(C + o) = make_float4(v[0], v[1], v[2], v[3]);
        }
    }
}

// ---------------- embedding --------------------------------------------------
__global__ void embed_kernel(const int* __restrict__ tok,
                             const float* __restrict__ emb,
                             float* __restrict__ x)
{
    int t = blockIdx.x, d = threadIdx.x;
    x[t * D + d] = emb[(size_t)tok[t] * D + d];
}

// ---------------- layernorm --------------------------------------------------
__global__ void ln_kernel(const float* __restrict__ x,
                          const float* __restrict__ w,
                          const float* __restrict__ b,
                          float* __restrict__ h)
{
    int t = blockIdx.x, d = threadIdx.x;
    float v = x[t * D + d];
    float s = v, s2 = v * v;
    #pragma unroll
    for (int o = 16; o > 0; o >>= 1) {
        s  += __shfl_xor_sync(0xffffffffu, s,  o);
        s2 += __shfl_xor_sync(0xffffffffu, s2, o);
    }
    __shared__ float ws[8], ws2[8];
    int wi = d >> 5;
    if ((d & 31) == 0) { ws[wi] = s; ws2[wi] = s2; }
    __syncthreads();
    if (d < 32) {
        float a  = (d < 8) ? ws[d]  : 0.f;
        float a2 = (d < 8) ? ws2[d] : 0.f;
        #pragma unroll
        for (int o = 4; o > 0; o >>= 1) {
            a  += __shfl_xor_sync(0xffffffffu, a,  o);
            a2 += __shfl_xor_sync(0xffffffffu, a2, o);
        }
        if (d == 0) { ws[0] = a; ws2[0] = a2; }
    }
    __syncthreads();
    float mu  = ws[0] * (1.f / D);
    float var = ws2[0] * (1.f / D) - mu * mu;
    float inv = rsqrtf(var + 1e-5f);
    h[t * D + d] = (v - mu) * inv * w[d] + b[d];
}

// ---------------- causal depthwise conv1d + SiLU ----------------------------
__global__ void conv_kernel(const float* __restrict__ xz,
                            const float* __restrict__ cw,
                            const float* __restrict__ cb,
                            float* __restrict__ xc)
{
    int t = blockIdx.x;
    int e = blockIdx.y * 256 + threadIdx.x;
    int l = t & (LL - 1);
    float acc = cb[e];
    #pragma unroll
    for (int k = 0; k < KC; k++) {
        int ll = l - (KC - 1) + k;
        if (ll >= 0)
            acc = fmaf(xz[(size_t)(t - (KC - 1) + k) * (2 * DI) + e], cw[e * KC + k], acc);
    }
    float s = 1.f / (1.f + __expf(-acc));
    xc[(size_t)t * DI + e] = acc * s;
}

// ---------------- selective scan + fused dt-proj + skip + gate ---------------
__global__ void scan_kernel(const float* __restrict__ dbc,
                            const float* __restrict__ dt_w,
                            const float* __restrict__ dt_b,
                            const float* __restrict__ xc,
                            const float* __restrict__ xz,
                            const float* __restrict__ A_log,
                            const float* __restrict__ Dskip,
                            float* __restrict__ y)
{
    int b = blockIdx.y;
    int tid = threadIdx.x;
    int e = blockIdx.x * 128 + tid;
    __shared__ float sBlk[8][64];

    float A[NS], h[NS], dtw[RR];
    #pragma unroll
    for (int n = 0; n < NS; n++) {
        A[n] = -__expf(A_log[e * NS + n]);
        h[n] = 0.f;
    }
    #pragma unroll
    for (int k = 0; k < RR; k++) dtw[k] = dt_w[e * RR + k];
    float dtb = dt_b[e];
    float Ds  = Dskip[e];

    for (int g = 0; g < LL / 8; g++) {
        __syncthreads();
        #pragma unroll
        for (int i = 0; i < 4; i++) {
            int id = tid + i * 128;
            int st = id >> 6, j = id & 63;
            if (j < 48) {
                int t = b * LL + g * 8 + st;
                sBlk[st][j] = dbc[(size_t)t * 48 + j];
            }
        }
        float xv8[8], zv8[8];
        #pragma unroll
        for (int s = 0; s < 8; s++) {
            int t = b * LL + g * 8 + s;
            xv8[s] = xc[(size_t)t * DI + e];
            zv8[s] = xz[(size_t)t * (2 * DI) + DI + e];
        }
        __syncthreads();
        #pragma unroll
        for (int s = 0; s < 8; s++) {
            int t = b * LL + g * 8 + s;
            float dtr = dtb;
            #pragma unroll
            for (int k = 0; k < RR; k++)
                dtr = fmaf(sBlk[s][k], dtw[k], dtr);
            float dtv = (dtr > 20.f) ? dtr : log1pf(expf(dtr));

            float xv = xv8[s];
            float du = dtv * xv;
            float acc = 0.f;
            #pragma unroll
            for (int n = 0; n < NS; n++) {
                float dA = __expf(dtv * A[n]);
                h[n] = fmaf(h[n], dA, du * sBlk[s][16 + n]);
                acc = fmaf(h[n], sBlk[s][32 + n], acc);
            }
            float zv = zv8[s];
            float sig = 1.f / (1.f + __expf(-zv));
            y[(size_t)t * DI + e] = (acc + xv * Ds) * (zv * sig);
        }
    }
}

// ---------------- host side --------------------------------------------------
extern "C" void kernel_launch(void* const* d_in, const int* in_sizes, int n_in,
                              void* d_out, int out_size)
{
    const int*   tok    = (const int*)  d_in[0];
    const float* emb    = (const float*)d_in[1];
    const float* ln_w   = (const float*)d_in[2];
    const float* ln_b   = (const float*)d_in[3];
    const float* in_w   = (const float*)d_in[4];
    const float* conv_w = (const float*)d_in[5];
    const float* conv_b = (const float*)d_in[6];
    const float* xp_w   = (const float*)d_in[7];
    const float* dt_w   = (const float*)d_in[8];
    const float* dt_b   = (const float*)d_in[9];
    const float* A_log  = (const float*)d_in[10];
    const float* Dskip  = (const float*)d_in[11];
    const float* out_w  = (const float*)d_in[12];
    const float* W1     = (const float*)d_in[13];
    const float* b1     = (const float*)d_in[14];
    const float* W2     = (const float*)d_in[15];
    const float* b2     = (const float*)d_in[16];
    float* out = (float*)d_out;

    cudaFuncSetAttribute(gemm_big<0>, cudaFuncAttributeMaxDynamicSharedMemorySize, SMEMG);
    cudaFuncSetAttribute(gemm_big<1>, cudaFuncAttributeMaxDynamicSharedMemorySize, SMEMG);
    cudaFuncSetAttribute(gemm_big<2>, cudaFuncAttributeMaxDynamicSharedMemorySize, SMEMG);
    cudaFuncSetAttribute(gemm_bigR<3>, cudaFuncAttributeMaxDynamicSharedMemorySize, SMEMR);

    float *px, *ph, *pxz, *pxc, *pdbc, *py, *ph1;
    cudaGetSymbolAddress((void**)&px,   g_x);
    cudaGetSymbolAddress((void**)&ph,   g_h);
    cudaGetSymbolAddress((void**)&pxz,  g_xz);
    cudaGetSymbolAddress((void**)&pxc,  g_xc);
    cudaGetSymbolAddress((void**)&pdbc, g_dbc);
    cudaGetSymbolAddress((void**)&py,   g_y);
    cudaGetSymbolAddress((void**)&ph1,  g_h1);

    embed_kernel<<<TT, D>>>(tok, emb, px);

    for (int l = 0; l < NL; l++) {
        const float* lw  = ln_w   + (size_t)l * D;
        const float* lb  = ln_b   + (size_t)l * D;
        const float* iw  = in_w   + (size_t)l * 2 * DI * D;
        const float* cw  = conv_w + (size_t)l * DI * KC;
        const float* cb  = conv_b + (size_t)l * DI;
        const float* xw  = xp_w   + (size_t)l * 48 * DI;
        const float* dw  = dt_w   + (size_t)l * DI * RR;
        const float* db  = dt_b   + (size_t)l * DI;
        const float* al  = A_log  + (size_t)l * DI * NS;
        const float* ds  = Dskip  + (size_t)l * DI;
        const float* ow  = out_w  + (size_t)l * D * DI;

        ln_kernel<<<TT, D>>>(px, lw, lb, ph);

        // xz = LN(x) @ in_w^T   (8192 x 1024 x 256)  [big tile, 256 blocks]
        gemm_big<0><<<dim3((2 * DI) / BNG, TT / BMG), 256, SMEMG>>>(
            ph, D, iw, D, pxz, 2 * DI, nullptr, 2 * DI, D);

        conv_kernel<<<dim3(TT, 2), 256>>>(pxz, cw, cb, pxc);

        // dbc = xc @ xp_w^T   (8192 x 48 x 512)  [TBM=64 -> 128 blocks]
        gemm2<0, 64><<<dim3(1, TT / 64), 256>>>(
            pxc, DI, xw, DI, pdbc, 48, nullptr, 48, DI);

        // scan with fused dt-projection
        scan_kernel<<<dim3(4, BB), 128>>>(pdbc, dw, db, pxc, pxz, al, ds, py);

        // x += y @ out_w^T   (8192 x 256 x 512)  [bigR, 128 blocks]
        gemm_bigR<3><<<dim3(D / BNG, TT / BMR), 128, SMEMR>>>(
            py, DI, ow, DI, px, D, px, D, DI);
    }

    // head: h1 = relu(x @ W1^T + b1)  [big tile]
    gemm_big<1><<<dim3(FF / BNG, TT / BMG), 256, SMEMG>>>(
        px, D, W1, D, ph1, FF, b1, FF, D);
    // logits = h1 @ W2^T + b2  [big tile]
    gemm_big<2><<<dim3(VV / BNG, TT / BMG), 256, SMEMG>>>(
        ph1, FF, W2, FF, out, VV, b2, VV, FF);
}